// round 5
// baseline (speedup 1.0000x reference)
#include <cuda_runtime.h>
#include <cuda_bf16.h>
#include <cstdint>

// Problem constants (fixed by the reference)
#define NT      131072
#define HID     2048
#define NRANKS  8
#define NEXP    16
#define NSEG    128            // NRANKS * NEXP
#define VEC     (HID / 4)      // 512 float4 per row

// Scratch (no device allocation allowed -> __device__ global)
__device__ int g_src[NT];      // per-output-row source row

// -------------------------------------------------------------------------
// Prep: fused setup + index. Every block redundantly computes both segment
// cumsums from counts (512 B, L2-resident) via warp-shuffle block scans,
// then each thread resolves one output row: writes g_src, permuted scale,
// idx. Block 0 also writes expert_token_num. Grid = NT/256 = 512 blocks.
//
// counts layout: counts[r * NEXP + e], rank-major (input order).
// Output segment order: p = e * NRANKS + r (expert-major, rank-minor).
// -------------------------------------------------------------------------
__global__ __launch_bounds__(256)
void moe_prep_kernel(const int* __restrict__ counts,
                     const float* __restrict__ scales,
                     float* __restrict__ out,
                     long long out_elems) {
    __shared__ int sc[NSEG];        // counts, input order
    __shared__ int s_in_off[NSEG];  // exclusive cumsum, input order
    __shared__ int s_off[NSEG + 1]; // exclusive cumsum, output order
    __shared__ int s_base[NSEG];    // input base per output segment
    __shared__ int warp_sums[8];    // [0..3]: scan1, [4..7]: scan2

    const int tid = threadIdx.x;
    if (tid < NSEG) sc[tid] = counts[tid];
    __syncthreads();

    int v1 = 0, v2 = 0, incl1 = 0, incl2 = 0;
    const int lane = tid & 31, w = tid >> 5;
    if (tid < NSEG) {
        v1 = sc[tid];
        incl1 = v1;
        #pragma unroll
        for (int d = 1; d < 32; d <<= 1) {
            int y = __shfl_up_sync(0xffffffffu, incl1, d);
            if (lane >= d) incl1 += y;
        }
        const int e = tid >> 3, r = tid & 7;
        v2 = sc[r * NEXP + e];
        incl2 = v2;
        #pragma unroll
        for (int d = 1; d < 32; d <<= 1) {
            int y = __shfl_up_sync(0xffffffffu, incl2, d);
            if (lane >= d) incl2 += y;
        }
        if (lane == 31) { warp_sums[w] = incl1; warp_sums[4 + w] = incl2; }
    }
    __syncthreads();

    if (tid < NSEG) {
        int base1 = 0, base2 = 0;
        for (int i = 0; i < w; i++) { base1 += warp_sums[i]; base2 += warp_sums[4 + i]; }
        s_in_off[tid] = base1 + incl1 - v1;                // exclusive
        s_off[tid]    = base2 + incl2 - v2;                // exclusive
        if (tid == NSEG - 1) s_off[NSEG] = base2 + incl2;  // == NT
    }
    __syncthreads();

    if (tid < NSEG) {
        const int e = tid >> 3, r = tid & 7;
        s_base[tid] = s_in_off[r * NEXP + e];
    }
    __syncthreads();

    const long long NH = (long long)NT * HID;

    // expert_token_num tail (block 0 only)
    if (blockIdx.x == 0 && tid < NEXP) {
        int s = 0;
        #pragma unroll
        for (int r = 0; r < NRANKS; r++) s += sc[r * NEXP + tid];
        long long pos = NH + 2LL * NT + tid;
        if (pos < out_elems) out[pos] = (float)s;
    }

    // per-output-row resolution
    const int row = blockIdx.x * 256 + tid;          // grid sized so row < NT
    int lo = 0, hi = NSEG - 1;
    #pragma unroll
    for (int it = 0; it < 7; it++) {
        int mid = (lo + hi + 1) >> 1;
        if (s_off[mid] <= row) lo = mid; else hi = mid - 1;
    }
    const int src = s_base[lo] + (row - s_off[lo]);

    g_src[row] = src;
    __stcs(&out[NH + row],      scales[src]);
    __stcs(&out[NH + NT + row], (float)src);   // idx < 2^24, exact in fp32
}

// -------------------------------------------------------------------------
// Gather: one block per output row, 128 threads x 4 float4 each.
// No barrier, no search, no smem: one uniform broadcast load of the
// source row, 4 front-batched streaming loads + 4 streaming stores.
// 16 resident blocks/SM smooths block-churn; MLP_p1 = 4 per thread.
// -------------------------------------------------------------------------
__global__ __launch_bounds__(128, 16)
void moe_gather_kernel(const float4* __restrict__ tokens,
                       float4* __restrict__ out4) {
    const int row = blockIdx.x;
    const int src = __ldg(&g_src[row]);              // uniform, L2-resident

    const float4* __restrict__ in = tokens + (long long)src * VEC;
    float4* __restrict__ o = out4 + (long long)row * VEC;

    const int t = threadIdx.x;
    float4 a = __ldcs(in + t);
    float4 b = __ldcs(in + t + 128);
    float4 c = __ldcs(in + t + 256);
    float4 d = __ldcs(in + t + 384);
    __stcs(o + t,       a);
    __stcs(o + t + 128, b);
    __stcs(o + t + 256, c);
    __stcs(o + t + 384, d);
}

extern "C" void kernel_launch(void* const* d_in, const int* in_sizes, int n_in,
                              void* d_out, int out_size) {
    const float* tokens = (const float*)d_in[0];
    const int*   counts = (const int*)d_in[1];   // [NRANKS, NEXP]
    const float* scales = (const float*)d_in[2];
    float* out = (float*)d_out;
    const long long out_elems = (long long)out_size;

    moe_prep_kernel<<<NT / 256, 256>>>(counts, scales, out, out_elems);
    moe_gather_kernel<<<NT, 128>>>((const float4*)tokens, (float4*)out);
}